// round 4
// baseline (speedup 1.0000x reference)
#include <cuda_runtime.h>
#include <cuda_bf16.h>
#include <math.h>

// Problem constants
#define PB 4
#define PN 2048
#define PF 256
#define PD 64      // NHID
#define PH 4       // NHEADS
#define PC 32      // NCLASS
#define PK1 256

// ---------------- scratch (device globals, no allocation) ----------------
__device__ float g_Wh1[PB * PH * PN * PD];   // [b,h,n,d]  8 MB
__device__ float g_f1[PB * PH * PN];
__device__ float g_f2[PB * PH * PN];
__device__ float g_h1[PB * PN * PH * PD];    // concat output of layer 1, 8 MB
__device__ float g_Wh2[PB * PN * PC];
__device__ float g_g1[PB * PN];
__device__ float g_g2[PB * PN];
__device__ float g_h2[PB * PN * PC];

// ---------------------------------------------------------------------------
// Kernel 1: Wh1[b,h,n,d] = sum_f x[b,n,f] * W[h,f,d]
// grid: (32 row-tiles, 16 bh), 256 threads, BM=64, BN=64, BK=32
// ---------------------------------------------------------------------------
__global__ void gemm1_kernel(const float* __restrict__ x,
                             const float* __restrict__ W,
                             float* __restrict__ Wh)
{
    __shared__ __align__(16) float As[32][68];  // [k][row], padded
    __shared__ __align__(16) float Bs[32][64];  // [k][d]

    const int it = blockIdx.x;
    const int bh = blockIdx.y;
    const int b  = bh >> 2;
    const int h  = bh & 3;
    const int i0 = it * 64;
    const int tid = threadIdx.x;
    const int tx = tid & 15, ty = tid >> 4;

    const float* A  = x + ((size_t)b * PN + i0) * PF;
    const float* Bw = W + (size_t)h * PF * PD;

    float acc[4][4];
#pragma unroll
    for (int u = 0; u < 4; u++)
#pragma unroll
        for (int v = 0; v < 4; v++) acc[u][v] = 0.f;

    for (int k0 = 0; k0 < PF; k0 += 32) {
        __syncthreads();
#pragma unroll
        for (int r = 0; r < 8; r++) {               // A tile 64x32
            int e = tid + 256 * r;
            int row = e >> 5, col = e & 31;
            As[col][row] = A[(size_t)row * PF + k0 + col];
        }
#pragma unroll
        for (int r = 0; r < 8; r++) {               // B tile 32x64
            int e = tid + 256 * r;
            int k = e >> 6, d = e & 63;
            Bs[k][d] = Bw[(size_t)(k0 + k) * PD + d];
        }
        __syncthreads();
#pragma unroll
        for (int k = 0; k < 32; k++) {
            float4 pa = *(const float4*)&As[k][ty * 4];
            float4 pb = *(const float4*)&Bs[k][tx * 4];
            acc[0][0] += pa.x * pb.x; acc[0][1] += pa.x * pb.y;
            acc[0][2] += pa.x * pb.z; acc[0][3] += pa.x * pb.w;
            acc[1][0] += pa.y * pb.x; acc[1][1] += pa.y * pb.y;
            acc[1][2] += pa.y * pb.z; acc[1][3] += pa.y * pb.w;
            acc[2][0] += pa.z * pb.x; acc[2][1] += pa.z * pb.y;
            acc[2][2] += pa.z * pb.z; acc[2][3] += pa.z * pb.w;
            acc[3][0] += pa.w * pb.x; acc[3][1] += pa.w * pb.y;
            acc[3][2] += pa.w * pb.z; acc[3][3] += pa.w * pb.w;
        }
    }

#pragma unroll
    for (int u = 0; u < 4; u++) {
        int n = i0 + ty * 4 + u;
        float4 o = make_float4(acc[u][0], acc[u][1], acc[u][2], acc[u][3]);
        *(float4*)&Wh[((size_t)bh * PN + n) * PD + tx * 4] = o;
    }
}

// ---------------------------------------------------------------------------
// Kernel 2: f1[b,h,n] = Wh1[b,h,n,:]·a1[h,:], f2 likewise. One warp per row.
// ---------------------------------------------------------------------------
__global__ void f12_kernel(const float* __restrict__ Wh,
                           const float* __restrict__ a1,
                           const float* __restrict__ a2,
                           float* __restrict__ f1, float* __restrict__ f2)
{
    int wrp = (blockIdx.x * (blockDim.x >> 5)) + (threadIdx.x >> 5);
    int lane = threadIdx.x & 31;
    if (wrp >= PB * PH * PN) return;
    int h = (wrp >> 11) & 3;
    const float* row = Wh + (size_t)wrp * PD;
    float v0 = row[lane], v1 = row[lane + 32];
    float s1 = v0 * a1[h * PD + lane] + v1 * a1[h * PD + lane + 32];
    float s2 = v0 * a2[h * PD + lane] + v1 * a2[h * PD + lane + 32];
#pragma unroll
    for (int o = 16; o; o >>= 1) {
        s1 += __shfl_xor_sync(0xffffffffu, s1, o);
        s2 += __shfl_xor_sync(0xffffffffu, s2, o);
    }
    if (lane == 0) { f1[wrp] = s1; f2[wrp] = s2; }
}

// ---------------------------------------------------------------------------
// Kernel 3: attention layer 1 (fused flash-style, no max needed since |s|<~4)
//   w_ij = adj ? exp(lrelu(f1_i + f2_j)) : 0 ; h_i = elu( (sum_j w V_j)/sum_j w )
// grid (32 itile, 4 h, 4 b), 256 thr. BM=64 rows, TJ=64 j-chunk, d=64.
// Ps stored TRANSPOSED [j][i] so GEMM inner is 2x LDS.128 / 16 FFMA.
// ---------------------------------------------------------------------------
__global__ void attn1_kernel(const float* __restrict__ f1,
                             const float* __restrict__ f2,
                             const float* __restrict__ Wh,
                             const int*   __restrict__ adj,
                             float* __restrict__ h1)
{
    __shared__ __align__(16) float Ps[64][68];   // [j][i]
    __shared__ __align__(16) float Vs[64][PD];   // [j][d]
    __shared__ float f1s[64], f2s[64], den[64], psum[64][4];

    const int it = blockIdx.x, h = blockIdx.y, b = blockIdx.z;
    const int i0 = it * 64;
    const int tid = threadIdx.x;
    const int tx = tid & 15, ty = tid >> 4;

    const float* f1p = f1 + ((size_t)(b * PH + h) * PN) + i0;
    const float* f2p = f2 + ((size_t)(b * PH + h) * PN);
    const float* Vb  = Wh + (size_t)(b * PH + h) * PN * PD;
    const int*   adjb = adj + ((size_t)b * PN + i0) * PN;

    if (tid < 64) { f1s[tid] = f1p[tid]; den[tid] = 0.f; }

    float acc[4][4];
#pragma unroll
    for (int u = 0; u < 4; u++)
#pragma unroll
        for (int v = 0; v < 4; v++) acc[u][v] = 0.f;

    for (int j0 = 0; j0 < PN; j0 += 64) {
        __syncthreads();
        {   // load V tile 64x64 = 1024 float4
            const float4* src = (const float4*)(Vb + (size_t)j0 * PD);
            float4* dst = (float4*)&Vs[0][0];
#pragma unroll
            for (int r = 0; r < 4; r++) dst[tid + 256 * r] = src[tid + 256 * r];
        }
        if (tid < 64) f2s[tid] = f2p[j0 + tid];
        __syncthreads();
        // build Ps (transposed) : 4096 elems, 16/thread, adj read coalesced in j
#pragma unroll
        for (int r = 0; r < 16; r++) {
            int e = tid + 256 * r;
            int i = e >> 6, j = e & 63;
            int a = adjb[(size_t)i * PN + j0 + j];
            float s = f1s[i] + f2s[j];
            s = s > 0.f ? s : 0.2f * s;
            Ps[j][i] = (a > 0) ? __expf(s) : 0.f;
        }
        __syncthreads();
        // partial row sums (i = tid&63, quarter seg = tid>>6)
        {
            int i = tid & 63, seg = tid >> 6;
            float sp = 0.f;
#pragma unroll
            for (int j = seg * 16; j < seg * 16 + 16; j++) sp += Ps[j][i];
            psum[i][seg] = sp;
        }
        // P @ V accumulate
#pragma unroll 8
        for (int kk = 0; kk < 64; kk++) {
            float4 pv = *(const float4*)&Ps[kk][ty * 4];
            float4 vv = *(const float4*)&Vs[kk][tx * 4];
            acc[0][0] += pv.x * vv.x; acc[0][1] += pv.x * vv.y;
            acc[0][2] += pv.x * vv.z; acc[0][3] += pv.x * vv.w;
            acc[1][0] += pv.y * vv.x; acc[1][1] += pv.y * vv.y;
            acc[1][2] += pv.y * vv.z; acc[1][3] += pv.y * vv.w;
            acc[2][0] += pv.z * vv.x; acc[2][1] += pv.z * vv.y;
            acc[2][2] += pv.z * vv.z; acc[2][3] += pv.z * vv.w;
            acc[3][0] += pv.w * vv.x; acc[3][1] += pv.w * vv.y;
            acc[3][2] += pv.w * vv.z; acc[3][3] += pv.w * vv.w;
        }
        __syncthreads();
        if (tid < 64)
            den[tid] += psum[tid][0] + psum[tid][1] + psum[tid][2] + psum[tid][3];
    }
    __syncthreads();

#pragma unroll
    for (int u = 0; u < 4; u++) {
        int i = ty * 4 + u;
        float d = den[i];
        float inv = d > 0.f ? 1.f / d : 0.f;
        float4 o = make_float4(acc[u][0] * inv, acc[u][1] * inv,
                               acc[u][2] * inv, acc[u][3] * inv);
        o.x = o.x > 0.f ? o.x : expm1f(o.x);
        o.y = o.y > 0.f ? o.y : expm1f(o.y);
        o.z = o.z > 0.f ? o.z : expm1f(o.z);
        o.w = o.w > 0.f ? o.w : expm1f(o.w);
        *(float4*)&h1[((size_t)b * PN + i0 + i) * (PH * PD) + h * PD + tx * 4] = o;
    }
}

// ---------------------------------------------------------------------------
// Kernel 4: Wh2 = h1 @ Wo  (+ per-row dots g1 = Wh2·ao1, g2 = Wh2·ao2)
// one warp per 2 rows; Wo staged in smem.
// ---------------------------------------------------------------------------
__global__ void gemm2_kernel(const float* __restrict__ h1,
                             const float* __restrict__ Wo,
                             const float* __restrict__ ao1,
                             const float* __restrict__ ao2,
                             float* __restrict__ Wh2,
                             float* __restrict__ g1, float* __restrict__ g2)
{
    __shared__ float Wos[PF * PC];
    for (int e = threadIdx.x; e < PF * PC; e += blockDim.x) Wos[e] = Wo[e];
    __syncthreads();

    int wrp = blockIdx.x * (blockDim.x >> 5) + (threadIdx.x >> 5);
    int lane = threadIdx.x & 31;
    int row0 = wrp * 2;
    if (row0 >= PB * PN) return;
    const float* r0 = h1 + (size_t)row0 * PF;
    const float* r1 = r0 + PF;

    float a0 = 0.f, a1v = 0.f;
#pragma unroll 4
    for (int k = 0; k < PF; k += 4) {
        float4 x0 = *(const float4*)(r0 + k);
        float4 x1 = *(const float4*)(r1 + k);
        a0 += x0.x * Wos[(k + 0) * PC + lane];
        a0 += x0.y * Wos[(k + 1) * PC + lane];
        a0 += x0.z * Wos[(k + 2) * PC + lane];
        a0 += x0.w * Wos[(k + 3) * PC + lane];
        a1v += x1.x * Wos[(k + 0) * PC + lane];
        a1v += x1.y * Wos[(k + 1) * PC + lane];
        a1v += x1.z * Wos[(k + 2) * PC + lane];
        a1v += x1.w * Wos[(k + 3) * PC + lane];
    }
    Wh2[(size_t)row0 * PC + lane] = a0;
    Wh2[(size_t)(row0 + 1) * PC + lane] = a1v;

    float s1 = a0 * ao1[lane], s2 = a0 * ao2[lane];
    float t1 = a1v * ao1[lane], t2 = a1v * ao2[lane];
#pragma unroll
    for (int o = 16; o; o >>= 1) {
        s1 += __shfl_xor_sync(0xffffffffu, s1, o);
        s2 += __shfl_xor_sync(0xffffffffu, s2, o);
        t1 += __shfl_xor_sync(0xffffffffu, t1, o);
        t2 += __shfl_xor_sync(0xffffffffu, t2, o);
    }
    if (lane == 0) {
        g1[row0] = s1; g2[row0] = s2;
        g1[row0 + 1] = t1; g2[row0 + 1] = t2;
    }
}

// ---------------------------------------------------------------------------
// Kernel 5: attention layer 2 (d=32) + elu epilogue -> h2
// grid (32 itile, 4 b). 256 thr, micro 4x2.
// ---------------------------------------------------------------------------
__global__ void attn2_kernel(const float* __restrict__ g1,
                             const float* __restrict__ g2,
                             const float* __restrict__ Wh2,
                             const int*   __restrict__ adj,
                             float* __restrict__ h2)
{
    __shared__ __align__(16) float Ps[64][68];
    __shared__ __align__(16) float Vs[64][PC];
    __shared__ float f1s[64], f2s[64], den[64], psum[64][4];

    const int it = blockIdx.x, b = blockIdx.y;
    const int i0 = it * 64;
    const int tid = threadIdx.x;
    const int tx = tid & 15, ty = tid >> 4;

    const float* f1p = g1 + (size_t)b * PN + i0;
    const float* f2p = g2 + (size_t)b * PN;
    const float* Vb  = Wh2 + (size_t)b * PN * PC;
    const int*   adjb = adj + ((size_t)b * PN + i0) * PN;

    if (tid < 64) { f1s[tid] = f1p[tid]; den[tid] = 0.f; }

    float acc[4][2];
#pragma unroll
    for (int u = 0; u < 4; u++) { acc[u][0] = 0.f; acc[u][1] = 0.f; }

    for (int j0 = 0; j0 < PN; j0 += 64) {
        __syncthreads();
        {   // V tile 64x32 = 512 float4
            const float4* src = (const float4*)(Vb + (size_t)j0 * PC);
            float4* dst = (float4*)&Vs[0][0];
            dst[tid] = src[tid];
            dst[tid + 256] = src[tid + 256];
        }
        if (tid < 64) f2s[tid] = f2p[j0 + tid];
        __syncthreads();
#pragma unroll
        for (int r = 0; r < 16; r++) {
            int e = tid + 256 * r;
            int i = e >> 6, j = e & 63;
            int a = adjb[(size_t)i * PN + j0 + j];
            float s = f1s[i] + f2s[j];
            s = s > 0.f ? s : 0.2f * s;
            Ps[j][i] = (a > 0) ? __expf(s) : 0.f;
        }
        __syncthreads();
        {
            int i = tid & 63, seg = tid >> 6;
            float sp = 0.f;
#pragma unroll
            for (int j = seg * 16; j < seg * 16 + 16; j++) sp += Ps[j][i];
            psum[i][seg] = sp;
        }
#pragma unroll 8
        for (int kk = 0; kk < 64; kk++) {
            float4 pv = *(const float4*)&Ps[kk][ty * 4];
            float2 vv = *(const float2*)&Vs[kk][tx * 2];
            acc[0][0] += pv.x * vv.x; acc[0][1] += pv.x * vv.y;
            acc[1][0] += pv.y * vv.x; acc[1][1] += pv.y * vv.y;
            acc[2][0] += pv.z * vv.x; acc[2][1] += pv.z * vv.y;
            acc[3][0] += pv.w * vv.x; acc[3][1] += pv.w * vv.y;
        }
        __syncthreads();
        if (tid < 64)
            den[tid] += psum[tid][0] + psum[tid][1] + psum[tid][2] + psum[tid][3];
    }
    __syncthreads();

#pragma unroll
    for (int u = 0; u < 4; u++) {
        int i = ty * 4 + u;
        float d = den[i];
        float inv = d > 0.f ? 1.f / d : 0.f;
        float2 o = make_float2(acc[u][0] * inv, acc[u][1] * inv);
        o.x = o.x > 0.f ? o.x : expm1f(o.x);
        o.y = o.y > 0.f ? o.y : expm1f(o.y);
        *(float2*)&h2[((size_t)b * PN + i0 + i) * PC + tx * 2] = o;
    }
}

// ---------------------------------------------------------------------------
// Kernel 6: gather + Linear(32,32) + PReLU + Linear(32,2). One warp per row.
// ---------------------------------------------------------------------------
__global__ void cls_kernel(const float* __restrict__ h2,
                           const int*   __restrict__ idcs,
                           const float* __restrict__ W1,
                           const float* __restrict__ b1,
                           const float* __restrict__ pw,
                           const float* __restrict__ W2,
                           const float* __restrict__ b2,
                           float* __restrict__ out)
{
    int wrp = blockIdx.x * (blockDim.x >> 5) + (threadIdx.x >> 5);
    int lane = threadIdx.x & 31;
    if (wrp >= PB * PK1) return;
    int b = wrp >> 8;
    int idx = idcs[wrp];
    const float* ef = h2 + ((size_t)b * PN + idx) * PC;

    float y = b1[lane];
#pragma unroll
    for (int d = 0; d < PC; d++) y += ef[d] * W1[d * PC + lane];
    y = y > 0.f ? y : pw[lane] * y;

    float o0 = y * W2[lane * 2 + 0];
    float o1 = y * W2[lane * 2 + 1];
#pragma unroll
    for (int o = 16; o; o >>= 1) {
        o0 += __shfl_xor_sync(0xffffffffu, o0, o);
        o1 += __shfl_xor_sync(0xffffffffu, o1, o);
    }
    if (lane == 0) {
        out[wrp * 2 + 0] = o0 + b2[0];
        out[wrp * 2 + 1] = o1 + b2[1];
    }
}

// ---------------------------------------------------------------------------
extern "C" void kernel_launch(void* const* d_in, const int* in_sizes, int n_in,
                              void* d_out, int out_size)
{
    const float* x    = (const float*)d_in[0];
    const int*   adj  = (const int*)  d_in[1];
    const int*   idcs = (const int*)  d_in[2];
    const float* W    = (const float*)d_in[3];
    const float* a1   = (const float*)d_in[4];
    const float* a2   = (const float*)d_in[5];
    const float* Wo   = (const float*)d_in[6];
    const float* ao1  = (const float*)d_in[7];
    const float* ao2  = (const float*)d_in[8];
    const float* W1   = (const float*)d_in[9];
    const float* b1   = (const float*)d_in[10];
    const float* pw   = (const float*)d_in[11];
    const float* W2   = (const float*)d_in[12];
    const float* b2   = (const float*)d_in[13];
    float* out = (float*)d_out;

    float *p_Wh1, *p_f1, *p_f2, *p_h1, *p_Wh2, *p_g1, *p_g2, *p_h2;
    cudaGetSymbolAddress((void**)&p_Wh1, g_Wh1);
    cudaGetSymbolAddress((void**)&p_f1,  g_f1);
    cudaGetSymbolAddress((void**)&p_f2,  g_f2);
    cudaGetSymbolAddress((void**)&p_h1,  g_h1);
    cudaGetSymbolAddress((void**)&p_Wh2, g_Wh2);
    cudaGetSymbolAddress((void**)&p_g1,  g_g1);
    cudaGetSymbolAddress((void**)&p_g2,  g_g2);
    cudaGetSymbolAddress((void**)&p_h2,  g_h2);

    gemm1_kernel<<<dim3(PN / 64, PB * PH), 256>>>(x, W, p_Wh1);
    f12_kernel<<<(PB * PH * PN) / 8, 256>>>(p_Wh1, a1, a2, p_f1, p_f2);
    attn1_kernel<<<dim3(PN / 64, PH, PB), 256>>>(p_f1, p_f2, p_Wh1, adj, p_h1);
    gemm2_kernel<<<(PB * PN / 2) / 8, 256>>>(p_h1, Wo, ao1, ao2, p_Wh2, p_g1, p_g2);
    attn2_kernel<<<dim3(PN / 64, PB), 256>>>(p_g1, p_g2, p_Wh2, adj, p_h2);
    cls_kernel<<<(PB * PK1) / 8, 256>>>(p_h2, idcs, W1, b1, pw, W2, b2, out);
}

// round 8
// speedup vs baseline: 2.1655x; 2.1655x over previous
#include <cuda_runtime.h>
#include <cuda_bf16.h>
#include <math.h>
#include <stdint.h>

// Problem constants
#define PB 4
#define PN 2048
#define PF 256
#define PD 64      // NHID
#define PH 4       // NHEADS
#define PC 32      // NCLASS
#define PK1 256

// ---------------- scratch (device globals, no allocation) ----------------
__device__ float g_Wh1[PB * PH * PN * PD];   // [bh,n,d]  8 MB
__device__ float g_h1[PB * PN * PH * PD];    // concat output of layer 1
__device__ float g_Wh2[PB * PN * PC];
__device__ float g_g1[PB * PN];
__device__ float g_g2[PB * PN];
__device__ float g_h2[PB * PN * PC];
__device__ uint32_t g_abits[PB * PN * (PN / 32)];       // adjacency bitmask, 2 MB
__device__ __nv_bfloat16 g_VtH[PB * PH * PD * PN];      // [g][d][n] hi
__device__ __nv_bfloat16 g_VtL[PB * PH * PD * PN];      // [g][d][n] lo
// factored exp terms (layer1: PB*PH*PN; layer2 reuses first PB*PN after attn1)
__device__ float g_e1p[PB * PH * PN];
__device__ float g_e1m[PB * PH * PN];
__device__ float g_e2p[PB * PH * PN];
__device__ float g_e2m[PB * PH * PN];

// =========================== helpers ===================================
__device__ __forceinline__ uint32_t smem_u32(const void* p) {
    uint32_t a;
    asm("{ .reg .u64 t; cvta.to.shared.u64 t, %1; cvt.u32.u64 %0, t; }"
        : "=r"(a) : "l"(p));
    return a;
}
// pack2bf(lo, hi): bf16x2 with lo in bits[0:16), hi in bits[16:32)
__device__ __forceinline__ uint32_t pack2bf(float lo, float hi) {
    uint32_t r;
    asm("cvt.rn.bf16x2.f32 %0, %1, %2;" : "=r"(r) : "f"(hi), "f"(lo));
    return r;
}
// split pair into bf16 hi part + bf16 residual part (packed)
__device__ __forceinline__ void split2(float x, float y, uint32_t& hi, uint32_t& lo) {
    hi = pack2bf(x, y);
    float hx = __uint_as_float(hi << 16);
    float hy = __uint_as_float(hi & 0xffff0000u);
    lo = pack2bf(x - hx, y - hy);
}
__device__ __forceinline__ void mma_bf16(float* d, const uint32_t* a, const uint32_t* b) {
    asm volatile(
        "mma.sync.aligned.m16n8k16.row.col.f32.bf16.bf16.f32 "
        "{%0,%1,%2,%3}, {%4,%5,%6,%7}, {%8,%9}, {%0,%1,%2,%3};"
        : "+f"(d[0]), "+f"(d[1]), "+f"(d[2]), "+f"(d[3])
        : "r"(a[0]), "r"(a[1]), "r"(a[2]), "r"(a[3]), "r"(b[0]), "r"(b[1]));
}
__device__ __forceinline__ void ldsm_x4(uint32_t* r, uint32_t addr) {
    asm volatile("ldmatrix.sync.aligned.m8n8.x4.shared.b16 {%0,%1,%2,%3}, [%4];"
                 : "=r"(r[0]), "=r"(r[1]), "=r"(r[2]), "=r"(r[3]) : "r"(addr));
}
// masked factored-exp element
__device__ __forceinline__ float pel(float ep, float em, float e2pv, float e2mv,
                                     uint32_t w, int bit) {
    float a = ep * e2pv;
    float bm = em * e2mv;
    float p = (a > 1.f) ? a : bm;
    return ((w >> bit) & 1u) ? p : 0.f;
}

// ---------------------------------------------------------------------------
// Kernel 1: Wh1[bh,n,d] = sum_f x[b,n,f] * W[h,f,d]
// ---------------------------------------------------------------------------
__global__ void gemm1_kernel(const float* __restrict__ x,
                             const float* __restrict__ W,
                             float* __restrict__ Wh)
{
    __shared__ __align__(16) float As[32][68];
    __shared__ __align__(16) float Bs[32][64];

    const int it = blockIdx.x;
    const int bh = blockIdx.y;
    const int b  = bh >> 2;
    const int h  = bh & 3;
    const int i0 = it * 64;
    const int tid = threadIdx.x;
    const int tx = tid & 15, ty = tid >> 4;

    const float* A  = x + ((size_t)b * PN + i0) * PF;
    const float* Bw = W + (size_t)h * PF * PD;

    float acc[4][4];
#pragma unroll
    for (int u = 0; u < 4; u++)
#pragma unroll
        for (int v = 0; v < 4; v++) acc[u][v] = 0.f;

    for (int k0 = 0; k0 < PF; k0 += 32) {
        __syncthreads();
#pragma unroll
        for (int r = 0; r < 8; r++) {
            int e = tid + 256 * r;
            int row = e >> 5, col = e & 31;
            As[col][row] = A[(size_t)row * PF + k0 + col];
        }
#pragma unroll
        for (int r = 0; r < 8; r++) {
            int e = tid + 256 * r;
            int k = e >> 6, d = e & 63;
            Bs[k][d] = Bw[(size_t)(k0 + k) * PD + d];
        }
        __syncthreads();
#pragma unroll
        for (int k = 0; k < 32; k++) {
            float4 pa = *(const float4*)&As[k][ty * 4];
            float4 pb = *(const float4*)&Bs[k][tx * 4];
            acc[0][0] += pa.x * pb.x; acc[0][1] += pa.x * pb.y;
            acc[0][2] += pa.x * pb.z; acc[0][3] += pa.x * pb.w;
            acc[1][0] += pa.y * pb.x; acc[1][1] += pa.y * pb.y;
            acc[1][2] += pa.y * pb.z; acc[1][3] += pa.y * pb.w;
            acc[2][0] += pa.z * pb.x; acc[2][1] += pa.z * pb.y;
            acc[2][2] += pa.z * pb.z; acc[2][3] += pa.z * pb.w;
            acc[3][0] += pa.w * pb.x; acc[3][1] += pa.w * pb.y;
            acc[3][2] += pa.w * pb.z; acc[3][3] += pa.w * pb.w;
        }
    }
#pragma unroll
    for (int u = 0; u < 4; u++) {
        int n = i0 + ty * 4 + u;
        float4 o = make_float4(acc[u][0], acc[u][1], acc[u][2], acc[u][3]);
        *(float4*)&Wh[((size_t)bh * PN + n) * PD + tx * 4] = o;
    }
}

// ---------------------------------------------------------------------------
// Kernel 2: f1/f2 projections + factored exps. One warp per row.
// ---------------------------------------------------------------------------
__global__ void f12_kernel(const float* __restrict__ Wh,
                           const float* __restrict__ a1,
                           const float* __restrict__ a2,
                           float* __restrict__ e1p, float* __restrict__ e1m,
                           float* __restrict__ e2p, float* __restrict__ e2m)
{
    int wrp = (blockIdx.x * (blockDim.x >> 5)) + (threadIdx.x >> 5);
    int lane = threadIdx.x & 31;
    if (wrp >= PB * PH * PN) return;
    int h = (wrp >> 11) & 3;
    const float* row = Wh + (size_t)wrp * PD;
    float v0 = row[lane], v1 = row[lane + 32];
    float s1 = v0 * a1[h * PD + lane] + v1 * a1[h * PD + lane + 32];
    float s2 = v0 * a2[h * PD + lane] + v1 * a2[h * PD + lane + 32];
#pragma unroll
    for (int o = 16; o; o >>= 1) {
        s1 += __shfl_xor_sync(0xffffffffu, s1, o);
        s2 += __shfl_xor_sync(0xffffffffu, s2, o);
    }
    if (lane == 0) {
        e1p[wrp] = __expf(s1); e1m[wrp] = __expf(0.2f * s1);
        e2p[wrp] = __expf(s2); e2m[wrp] = __expf(0.2f * s2);
    }
}

// ---------------------------------------------------------------------------
// Kernel 3: pack adj>0 into bitmask
// ---------------------------------------------------------------------------
__global__ void adjbits_kernel(const int* __restrict__ adj,
                               uint32_t* __restrict__ bits)
{
    size_t t = (size_t)blockIdx.x * 256 + threadIdx.x;
    int a = adj[t];
    unsigned m = __ballot_sync(0xffffffffu, a > 0);
    if ((threadIdx.x & 31) == 0) bits[t >> 5] = m;
}

// ---------------------------------------------------------------------------
// Kernel 4: transpose + bf16 hi/lo split: src[g][n][DD] fp32 -> dh/dl[g][DD][n]
// ---------------------------------------------------------------------------
template<int DD>
__global__ void tsplit_kernel(const float* __restrict__ src,
                              __nv_bfloat16* __restrict__ dh,
                              __nv_bfloat16* __restrict__ dl)
{
    __shared__ float sm[128][DD + 1];
    const int g = blockIdx.y, n0 = blockIdx.x * 128;
    const int tid = threadIdx.x;
    const float* sp = src + ((size_t)g * PN + n0) * DD;
#pragma unroll 4
    for (int e = tid; e < 128 * DD; e += 256) {
        int n = e / DD, d = e % DD;
        sm[n][d] = sp[(size_t)n * DD + d];
    }
    __syncthreads();
#pragma unroll 4
    for (int e = tid; e < 128 * DD; e += 256) {
        int d = e >> 7, n = e & 127;
        float v = sm[n][d];
        __nv_bfloat16 hv = __float2bfloat16(v);
        float r = v - __bfloat162float(hv);
        size_t o = ((size_t)g * DD + d) * PN + n0 + n;
        dh[o] = hv;
        dl[o] = __float2bfloat16(r);
    }
}

// ---------------------------------------------------------------------------
// Kernel 5: exps for layer-2 factored attention scores
// ---------------------------------------------------------------------------
__global__ void expfac_kernel(const float* __restrict__ s1,
                              const float* __restrict__ s2,
                              float* __restrict__ e1p, float* __restrict__ e1m,
                              float* __restrict__ e2p, float* __restrict__ e2m)
{
    int t = blockIdx.x * 256 + threadIdx.x;
    if (t >= PB * PN) return;
    float a = s1[t], b = s2[t];
    e1p[t] = __expf(a); e1m[t] = __expf(0.2f * a);
    e2p[t] = __expf(b); e2m[t] = __expf(0.2f * b);
}

// ---------------------------------------------------------------------------
// Kernel 6: warp-MMA attention. Block = 256 thr = 8 warps x 16 rows = 128 rows.
//   P built directly into mma A-fragments in registers (factored exp, no MUFU).
//   V tiles (pre-split bf16 hi/lo, [d][n] layout) staged in SW128-swizzled
//   smem, read via ldmatrix.x4 as B fragments. 3-term bf16 product split.
//   Row sums accumulated in registers; epilogue normalizes + elu.
// ---------------------------------------------------------------------------
template<int NC>
__global__ void __launch_bounds__(256) attn_mma_kernel(
    const float* __restrict__ e1pg, const float* __restrict__ e1mg,
    const float* __restrict__ e2pg, const float* __restrict__ e2mg,
    const __nv_bfloat16* __restrict__ VtH, const __nv_bfloat16* __restrict__ VtL,
    const uint32_t* __restrict__ abits, float* __restrict__ out,
    int outStride, int hshift)
{
    __shared__ __align__(128) char VsH[NC * 128];   // [d][64 j] bf16, SW128
    __shared__ __align__(128) char VsL[NC * 128];
    __shared__ float e2ps[64], e2ms[64];
    __shared__ uint32_t aws[128][2];

    const int tid = threadIdx.x;
    const int lane = tid & 31, wid = tid >> 5;
    const int g = blockIdx.y;
    const int b = g >> hshift;
    const int h = g & ((1 << hshift) - 1);
    const int i0 = blockIdx.x * 128;

    const int r0 = wid * 16 + (lane >> 2);   // tile row (0..127)
    const int r1 = r0 + 8;
    const int cq = (lane & 3) * 2;           // fragment col base

    const float E1p0 = e1pg[(size_t)g * PN + i0 + r0];
    const float E1m0 = e1mg[(size_t)g * PN + i0 + r0];
    const float E1p1 = e1pg[(size_t)g * PN + i0 + r1];
    const float E1m1 = e1mg[(size_t)g * PN + i0 + r1];

    const float* e2pp = e2pg + (size_t)g * PN;
    const float* e2mp = e2mg + (size_t)g * PN;
    const __nv_bfloat16* vh = VtH + (size_t)g * NC * PN;
    const __nv_bfloat16* vl = VtL + (size_t)g * NC * PN;
    const uint32_t* abase = abits + ((size_t)b * PN + i0) * (PN / 32);

    const uint32_t sVH = smem_u32(VsH), sVL = smem_u32(VsL);
    // ldmatrix source offset pattern for this lane (chunk-invariant part)
    const int vrow_l = ((lane >> 4) << 3) + (lane & 7);
    const int vcol_l = ((lane >> 3) & 1) << 3;

    float acc[NC / 8][4];
#pragma unroll
    for (int nt = 0; nt < NC / 8; nt++)
#pragma unroll
        for (int u = 0; u < 4; u++) acc[nt][u] = 0.f;
    float rs0 = 0.f, rs1 = 0.f;

    for (int c = 0; c < 32; c++) {
        const int j0 = c * 64;
        __syncthreads();                      // previous chunk's reads done
        if (tid < 64) {
            e2ps[tid] = e2pp[j0 + tid];
            e2ms[tid] = e2mp[j0 + tid];
        }
        aws[tid >> 1][tid & 1] =
            abase[(size_t)(tid >> 1) * (PN / 32) + (j0 >> 5) + (tid & 1)];
#pragma unroll
        for (int t = tid; t < NC * 8; t += 256) {
            int d = t >> 3, q = t & 7;
            uint32_t off = d * 128 + q * 16;
            uint32_t sw = off ^ ((off >> 3) & 0x70);
            *(uint4*)(VsH + sw) = *(const uint4*)(vh + (size_t)d * PN + j0 + q * 8);
            *(uint4*)(VsL + sw) = *(const uint4*)(vl + (size_t)d * PN + j0 + q * 8);
        }
        __syncthreads();                      // stages visible

        const uint32_t aw00 = aws[r0][0], aw01 = aws[r0][1];
        const uint32_t aw10 = aws[r1][0], aw11 = aws[r1][1];

#pragma unroll
        for (int ks = 0; ks < 4; ks++) {
            const int cA = ks * 16 + cq;
            const float2 P2a = *(const float2*)&e2ps[cA];
            const float2 M2a = *(const float2*)&e2ms[cA];
            const float2 P2b = *(const float2*)&e2ps[cA + 8];
            const float2 M2b = *(const float2*)&e2ms[cA + 8];
            const uint32_t w0 = (ks < 2) ? aw00 : aw01;
            const uint32_t w1 = (ks < 2) ? aw10 : aw11;
            const int bb = (ks & 1) * 16 + cq;

            float p00 = pel(E1p0, E1m0, P2a.x, M2a.x, w0, bb);
            float p01 = pel(E1p0, E1m0, P2a.y, M2a.y, w0, bb + 1);
            float p02 = pel(E1p0, E1m0, P2b.x, M2b.x, w0, bb + 8);
            float p03 = pel(E1p0, E1m0, P2b.y, M2b.y, w0, bb + 9);
            float p10 = pel(E1p1, E1m1, P2a.x, M2a.x, w1, bb);
            float p11 = pel(E1p1, E1m1, P2a.y, M2a.y, w1, bb + 1);
            float p12 = pel(E1p1, E1m1, P2b.x, M2b.x, w1, bb + 8);
            float p13 = pel(E1p1, E1m1, P2b.y, M2b.y, w1, bb + 9);
            rs0 += (p00 + p01) + (p02 + p03);
            rs1 += (p10 + p11) + (p12 + p13);

            uint32_t aH[4], aL[4];
            split2(p00, p01, aH[0], aL[0]);
            split2(p10, p11, aH[1], aL[1]);
            split2(p02, p03, aH[2], aL[2]);
            split2(p12, p13, aH[3], aL[3]);

            // B fragments + mma: n-pairs of 16
#pragma unroll
            for (int np = 0; np < NC / 16; np++) {
                int vrow = np * 16 + vrow_l;
                int vcol = ks * 16 + vcol_l;
                uint32_t off = vrow * 128 + vcol * 2;
                off ^= (off >> 3) & 0x70;
                uint32_t bH[4], bL[4];
                ldsm_x4(bH, sVH + off);
                ldsm_x4(bL, sVL + off);
                mma_bf16(acc[2 * np], aH, bH);
                mma_bf16(acc[2 * np], aH, bL);
                mma_bf16(acc[2 * np], aL, bH);
                mma_bf16(acc[2 * np + 1], aH, bH + 2);
                mma_bf16(acc[2 * np + 1], aH, bL + 2);
                mma_bf16(acc[2 * np + 1], aL, bH + 2);
            }
        }
    }

    // reduce row sums across the 4 lanes sharing rows
    rs0 += __shfl_xor_sync(0xffffffffu, rs0, 1);
    rs0 += __shfl_xor_sync(0xffffffffu, rs0, 2);
    rs1 += __shfl_xor_sync(0xffffffffu, rs1, 1);
    rs1 += __shfl_xor_sync(0xffffffffu, rs1, 2);
    float inv0 = rs0 > 0.f ? 1.f / rs0 : 0.f;
    float inv1 = rs1 > 0.f ? 1.f / rs1 : 0.f;

    float* o0 = out + ((size_t)b * PN + i0 + r0) * outStride + h * NC;
    float* o1 = out + ((size_t)b * PN + i0 + r1) * outStride + h * NC;
#pragma unroll
    for (int nt = 0; nt < NC / 8; nt++) {
        int col = nt * 8 + cq;
        float2 v0 = make_float2(acc[nt][0] * inv0, acc[nt][1] * inv0);
        float2 v1 = make_float2(acc[nt][2] * inv1, acc[nt][3] * inv1);
        v0.x = v0.x > 0.f ? v0.x : expm1f(v0.x);
        v0.y = v0.y > 0.f ? v0.y : expm1f(v0.y);
        v1.x = v1.x > 0.f ? v1.x : expm1f(v1.x);
        v1.y = v1.y > 0.f ? v1.y : expm1f(v1.y);
        *(float2*)(o0 + col) = v0;
        *(float2*)(o1 + col) = v1;
    }
}

// ---------------------------------------------------------------------------
// Kernel 7: Wh2 = h1 @ Wo (+ g1/g2 dots). Warp per 4 rows.
// ---------------------------------------------------------------------------
__global__ void gemm2_kernel(const float* __restrict__ h1,
                             const float* __restrict__ Wo,
                             const float* __restrict__ ao1,
                             const float* __restrict__ ao2,
                             float* __restrict__ Wh2,
                             float* __restrict__ g1, float* __restrict__ g2)
{
    __shared__ float Wos[PF * PC];
    for (int e = threadIdx.x; e < PF * PC; e += blockDim.x) Wos[e] = Wo[e];
    __syncthreads();

    int wrp = blockIdx.x * (blockDim.x >> 5) + (threadIdx.x >> 5);
    int lane = threadIdx.x & 31;
    int row0 = wrp * 4;
    if (row0 >= PB * PN) return;
    const float* p0 = h1 + (size_t)row0 * PF;

    float a0 = 0.f, a1v = 0.f, a2v = 0.f, a3v = 0.f;
#pragma unroll 4
    for (int k = 0; k < PF; k += 4) {
        float w0 = Wos[(k + 0) * PC + lane];
        float w1 = Wos[(k + 1) * PC + lane];
        float w2 = Wos[(k + 2) * PC + lane];
        float w3 = Wos[(k + 3) * PC + lane];
        float4 x0 = *(const float4*)(p0 + k);
        float4 x1 = *(const float4*)(p0 + PF + k);
        float4 x2 = *(const float4*)(p0 + 2 * PF + k);
        float4 x3 = *(const float4*)(p0 + 3 * PF + k);
        a0  += x0.x * w0 + x0.y * w1 + x0.z * w2 + x0.w * w3;
        a1v += x1.x * w0 + x1.y * w1 + x1.z * w2 + x1.w * w3;
        a2v += x2.x * w0 + x2.y * w1 + x2.z * w2 + x2.w * w3;
        a3v += x3.x * w0 + x3.y * w1 + x3.z * w2 + x3.w * w3;
    }
    Wh2[(size_t)(row0 + 0) * PC + lane] = a0;
    Wh2[(size_t)(row0 + 1) * PC + lane] = a1v;
    Wh2[(size_t)(row0 + 2) * PC + lane] = a2v;
    Wh2[(size_t)(row0 + 3) * PC + lane] = a3v;

    float o1 = ao1[lane], o2 = ao2[lane];
    float s0 = a0 * o1, d0 = a0 * o2;
    float s1 = a1v * o1, d1 = a1v * o2;
    float s2 = a2v * o1, d2 = a2v * o2;
    float s3 = a3v * o1, d3 = a3v * o2;
#pragma unroll
    for (int o = 16; o; o >>= 1) {
        s0 += __shfl_xor_sync(0xffffffffu, s0, o);
        d0 += __shfl_xor_sync(0xffffffffu, d0, o);
        s1 += __shfl_xor_sync(0xffffffffu, s1, o);
        d1 += __shfl_xor_sync(0xffffffffu, d1, o);
        s2 += __shfl_xor_sync(0xffffffffu, s2, o);
        d2 += __shfl_xor_sync(0xffffffffu, d2, o);
        s3 += __shfl_xor_sync(0xffffffffu, s3, o);
        d3 += __shfl_xor_sync(0xffffffffu, d3, o);
    }
    if (lane == 0) {
        g1[row0 + 0] = s0; g2[row0 + 0] = d0;
        g1[row0 + 1] = s1; g2[row0 + 1] = d1;
        g1[row0 + 2] = s2; g2[row0 + 2] = d2;
        g1[row0 + 3] = s3; g2[row0 + 3] = d3;
    }
}

// ---------------------------------------------------------------------------
// Kernel 8: gather + Linear(32,32) + PReLU + Linear(32,2)
// ---------------------------------------------------------------------------
__global__ void cls_kernel(const float* __restrict__ h2,
                           const int*   __restrict__ idcs,
                           const float* __restrict__ W1,
                           const float* __restrict__ b1,
                           const float* __restrict__ pw,
                           const float* __restrict__ W2,
                           const float* __restrict__ b2,
                           float* __restrict__ out)
{
    int wrp = blockIdx.x * (blockDim.x >> 5) + (threadIdx.x >> 5);
    int lane = threadIdx.x & 31;
    if (wrp >= PB * PK1) return;
    int b = wrp >> 8;
    int idx = idcs[wrp];
    const float* ef = h2 + ((size_t)b * PN + idx) * PC;

    float y = b1[lane];
#pragma unroll
    for (int d = 0; d < PC; d++) y += ef[d] * W1[d * PC + lane];
    y = y > 0.f ? y : pw[lane] * y;

    float o0 = y * W2[lane * 2 + 0];
    float o1 = y * W2[lane * 2 + 1];
#pragma unroll
    for (int o = 16; o; o >>= 1) {
        o0 += __shfl_xor_sync(0xffffffffu, o0, o);
        o1 += __shfl_xor_sync(0xffffffffu, o1, o);
    }
    if (lane == 0) {
        out[wrp * 2 + 0] = o0 + b2[0];
        out[wrp * 2 + 1] = o1 + b2[1];
    }
}

// ---------------------------------------------------------------------------
extern "C" void kernel_launch(void* const* d_in, const int* in_sizes, int n_in,
                              void* d_out, int out_size)
{
    const float* x    = (const float*)d_in[0];
    const int*   adj  = (const int*)  d_in[1];
    const int*   idcs = (const int*)  d_in[2];
    const float* W    = (const float*)d_in[3];
    const float* a1   = (const float*)d_in[4];
    const float* a2   = (const float*)d_in[5];
    const float* Wo   = (const float*)d_in[6];
    const float* ao1  = (const float*)d_in[7];
    const float* ao2  = (const float*)d_in[8];
    const float* W1   = (const float*)d_in[9];
    const float* b1   = (const float*)d_in[10];
    const float* pw   = (const float*)d_in[11];
    const float* W2   = (const float*)d_in[12];
    const float* b2   = (const float*)d_in[13];
    float* out = (float*)d_out;

    float *p_Wh1, *p_h1, *p_Wh2, *p_g1, *p_g2, *p_h2;
    float *p_e1p, *p_e1m, *p_e2p, *p_e2m;
    uint32_t* p_ab;
    __nv_bfloat16 *p_vh, *p_vl;
    cudaGetSymbolAddress((void**)&p_Wh1, g_Wh1);
    cudaGetSymbolAddress((void**)&p_h1,  g_h1);
    cudaGetSymbolAddress((void**)&p_Wh2, g_Wh2);
    cudaGetSymbolAddress((void**)&p_g1,  g_g1);
    cudaGetSymbolAddress((void**)&p_g2,  g_g2);
    cudaGetSymbolAddress((void**)&p_h2,  g_h2);
    cudaGetSymbolAddress((void**)&p_ab,  g_abits);
    cudaGetSymbolAddress((void**)&p_vh,  g_VtH);
    cudaGetSymbolAddress((void**)&p_vl,  g_VtL);
    cudaGetSymbolAddress((void**)&p_e1p, g_e1p);
    cudaGetSymbolAddress((void**)&p_e1m, g_e1m);
    cudaGetSymbolAddress((void**)&p_e2p, g_e2p);
    cudaGetSymbolAddress((void**)&p_e2m, g_e2m);

    gemm1_kernel<<<dim3(PN / 64, PB * PH), 256>>>(x, W, p_Wh1);
    f12_kernel<<<(PB * PH * PN) / 8, 256>>>(p_Wh1, a1, a2,
                                            p_e1p, p_e1m, p_e2p, p_e2m);
    adjbits_kernel<<<(PB * PN * PN) / 256, 256>>>(adj, p_ab);
    tsplit_kernel<PD><<<dim3(PN / 128, PB * PH), 256>>>(p_Wh1, p_vh, p_vl);

    attn_mma_kernel<PD><<<dim3(PN / 128, PB * PH), 256>>>(
        p_e1p, p_e1m, p_e2p, p_e2m, p_vh, p_vl, p_ab, p_h1, PH * PD, 2);

    gemm2_kernel<<<(PB * PN / 4) / 8, 256>>>(p_h1, Wo, ao1, ao2, p_Wh2, p_g1, p_g2);
    expfac_kernel<<<(PB * PN + 255) / 256, 256>>>(p_g1, p_g2,
                                                  p_e1p, p_e1m, p_e2p, p_e2m);
    tsplit_kernel<PC><<<dim3(PN / 128, PB), 256>>>(p_Wh2, p_vh, p_vl);

    attn_mma_kernel<PC><<<dim3(PN / 128, PB), 256>>>(
        p_e1p, p_e1m, p_e2p, p_e2m, p_vh, p_vl, p_ab, p_h2, PC, 0);

    cls_kernel<<<(PB * PK1) / 8, 256>>>(p_h2, idcs, W1, b1, pw, W2, b2, out);
}

// round 9
// speedup vs baseline: 2.6967x; 1.2453x over previous
#include <cuda_runtime.h>
#include <cuda_fp16.h>
#include <math.h>
#include <stdint.h>

// Problem constants
#define PB 4
#define PN 2048
#define PF 256
#define PD 64      // NHID
#define PH 4       // NHEADS
#define PC 32      // NCLASS
#define PK1 256

// ---------------- scratch (device globals, no allocation) ----------------
__device__ float g_Wh1[PB * PH * PN * PD];   // [bh,n,d]  8 MB
__device__ float g_h1[PB * PN * PH * PD];    // concat output of layer 1
__device__ float g_Wh2[PB * PN * PC];
__device__ float g_h2[PB * PN * PC];
__device__ uint32_t g_abits[PB * PN * (PN / 32)];  // adjacency bitmask, 2 MB
__device__ __half g_VtH[PB * PH * PD * PN];        // [g][d][n] hi
__device__ __half g_VtL[PB * PH * PD * PN];        // [g][d][n] lo (residual)
// factored exp terms (layer1: PB*PH*PN; layer2 reuses first PB*PN)
__device__ float g_e1p[PB * PH * PN];
__device__ float g_e1m[PB * PH * PN];
__device__ float g_e2p[PB * PH * PN];
__device__ float g_e2m[PB * PH * PN];

// =========================== helpers ===================================
__device__ __forceinline__ uint32_t smem_u32(const void* p) {
    uint32_t a;
    asm("{ .reg .u64 t; cvta.to.shared.u64 t, %1; cvt.u32.u64 %0, t; }"
        : "=r"(a) : "l"(p));
    return a;
}
// pack2h(lo, hi): f16x2 with lo in bits[0:16), hi in bits[16:32)
__device__ __forceinline__ uint32_t pack2h(float lo, float hi) {
    uint32_t r;
    asm("cvt.rn.f16x2.f32 %0, %1, %2;" : "=r"(r) : "f"(hi), "f"(lo));
    return r;
}
__device__ __forceinline__ void mma_f16(float* d, const uint32_t* a, const uint32_t* b) {
    asm volatile(
        "mma.sync.aligned.m16n8k16.row.col.f32.f16.f16.f32 "
        "{%0,%1,%2,%3}, {%4,%5,%6,%7}, {%8,%9}, {%0,%1,%2,%3};"
        : "+f"(d[0]), "+f"(d[1]), "+f"(d[2]), "+f"(d[3])
        : "r"(a[0]), "r"(a[1]), "r"(a[2]), "r"(a[3]), "r"(b[0]), "r"(b[1]));
}
__device__ __forceinline__ void ldsm_x4(uint32_t* r, uint32_t addr) {
    asm volatile("ldmatrix.sync.aligned.m8n8.x4.shared.b16 {%0,%1,%2,%3}, [%4];"
                 : "=r"(r[0]), "=r"(r[1]), "=r"(r[2]), "=r"(r[3]) : "r"(addr));
}
// masked factored-exp element
__device__ __forceinline__ float pel(float ep, float em, float e2pv, float e2mv,
                                     uint32_t w, int bit) {
    float a = ep * e2pv;
    float bm = em * e2mv;
    float p = (a > 1.f) ? a : bm;
    return ((w >> bit) & 1u) ? p : 0.f;
}

// ---------------------------------------------------------------------------
// Kernel 1: Wh1[bh,n,d] = sum_f x[b,n,f] * W[h,f,d]
// ---------------------------------------------------------------------------
__global__ void gemm1_kernel(const float* __restrict__ x,
                             const float* __restrict__ W,
                             float* __restrict__ Wh)
{
    __shared__ __align__(16) float As[32][68];
    __shared__ __align__(16) float Bs[32][64];

    const int it = blockIdx.x;
    const int bh = blockIdx.y;
    const int b  = bh >> 2;
    const int h  = bh & 3;
    const int i0 = it * 64;
    const int tid = threadIdx.x;
    const int tx = tid & 15, ty = tid >> 4;

    const float* A  = x + ((size_t)b * PN + i0) * PF;
    const float* Bw = W + (size_t)h * PF * PD;

    float acc[4][4];
#pragma unroll
    for (int u = 0; u < 4; u++)
#pragma unroll
        for (int v = 0; v < 4; v++) acc[u][v] = 0.f;

    for (int k0 = 0; k0 < PF; k0 += 32) {
        __syncthreads();
#pragma unroll
        for (int r = 0; r < 8; r++) {
            int e = tid + 256 * r;
            int row = e >> 5, col = e & 31;
            As[col][row] = A[(size_t)row * PF + k0 + col];
        }
#pragma unroll
        for (int r = 0; r < 8; r++) {
            int e = tid + 256 * r;
            int k = e >> 6, d = e & 63;
            Bs[k][d] = Bw[(size_t)(k0 + k) * PD + d];
        }
        __syncthreads();
#pragma unroll
        for (int k = 0; k < 32; k++) {
            float4 pa = *(const float4*)&As[k][ty * 4];
            float4 pb = *(const float4*)&Bs[k][tx * 4];
            acc[0][0] += pa.x * pb.x; acc[0][1] += pa.x * pb.y;
            acc[0][2] += pa.x * pb.z; acc[0][3] += pa.x * pb.w;
            acc[1][0] += pa.y * pb.x; acc[1][1] += pa.y * pb.y;
            acc[1][2] += pa.y * pb.z; acc[1][3] += pa.y * pb.w;
            acc[2][0] += pa.z * pb.x; acc[2][1] += pa.z * pb.y;
            acc[2][2] += pa.z * pb.z; acc[2][3] += pa.z * pb.w;
            acc[3][0] += pa.w * pb.x; acc[3][1] += pa.w * pb.y;
            acc[3][2] += pa.w * pb.z; acc[3][3] += pa.w * pb.w;
        }
    }
#pragma unroll
    for (int u = 0; u < 4; u++) {
        int n = i0 + ty * 4 + u;
        float4 o = make_float4(acc[u][0], acc[u][1], acc[u][2], acc[u][3]);
        *(float4*)&Wh[((size_t)bh * PN + n) * PD + tx * 4] = o;
    }
}

// ---------------------------------------------------------------------------
// Kernel 2: f1/f2 projections + factored exps. One warp per row.
// ---------------------------------------------------------------------------
__global__ void f12_kernel(const float* __restrict__ Wh,
                           const float* __restrict__ a1,
                           const float* __restrict__ a2,
                           float* __restrict__ e1p, float* __restrict__ e1m,
                           float* __restrict__ e2p, float* __restrict__ e2m)
{
    int wrp = (blockIdx.x * (blockDim.x >> 5)) + (threadIdx.x >> 5);
    int lane = threadIdx.x & 31;
    if (wrp >= PB * PH * PN) return;
    int h = (wrp >> 11) & 3;
    const float* row = Wh + (size_t)wrp * PD;
    float v0 = row[lane], v1 = row[lane + 32];
    float s1 = v0 * a1[h * PD + lane] + v1 * a1[h * PD + lane + 32];
    float s2 = v0 * a2[h * PD + lane] + v1 * a2[h * PD + lane + 32];
#pragma unroll
    for (int o = 16; o; o >>= 1) {
        s1 += __shfl_xor_sync(0xffffffffu, s1, o);
        s2 += __shfl_xor_sync(0xffffffffu, s2, o);
    }
    if (lane == 0) {
        e1p[wrp] = __expf(s1); e1m[wrp] = __expf(0.2f * s1);
        e2p[wrp] = __expf(s2); e2m[wrp] = __expf(0.2f * s2);
    }
}

// ---------------------------------------------------------------------------
// Kernel 3: pack adj>0 into bitmask
// ---------------------------------------------------------------------------
__global__ void adjbits_kernel(const int* __restrict__ adj,
                               uint32_t* __restrict__ bits)
{
    size_t t = (size_t)blockIdx.x * 256 + threadIdx.x;
    int a = adj[t];
    unsigned m = __ballot_sync(0xffffffffu, a > 0);
    if ((threadIdx.x & 31) == 0) bits[t >> 5] = m;
}

// ---------------------------------------------------------------------------
// Kernel 4: transpose + fp16 hi/lo split: src[g][n][DD] fp32 -> dh/dl[g][DD][n]
// ---------------------------------------------------------------------------
template<int DD>
__global__ void tsplit_kernel(const float* __restrict__ src,
                              __half* __restrict__ dh,
                              __half* __restrict__ dl)
{
    __shared__ float sm[128][DD + 1];
    const int g = blockIdx.y, n0 = blockIdx.x * 128;
    const int tid = threadIdx.x;
    const float* sp = src + ((size_t)g * PN + n0) * DD;
#pragma unroll 4
    for (int e = tid; e < 128 * DD; e += 256) {
        int n = e / DD, d = e % DD;
        sm[n][d] = sp[(size_t)n * DD + d];
    }
    __syncthreads();
#pragma unroll 4
    for (int e = tid; e < 128 * DD; e += 256) {
        int d = e >> 7, n = e & 127;
        float v = sm[n][d];
        __half hv = __float2half_rn(v);
        float r = v - __half2float(hv);
        size_t o = ((size_t)g * DD + d) * PN + n0 + n;
        dh[o] = hv;
        dl[o] = __float2half_rn(r);
    }
}

// ---------------------------------------------------------------------------
// Kernel 5: warp-MMA attention, fp16 2-term (A=P single fp16, V hi+lo fp16).
//   Block = 256 thr = 8 warps x 16 rows = 128 rows. P built directly into
//   A-fragments from factored exps (no MUFU, no smem P). 4 mma per 16x16x16
//   tile-pair instead of 6 (R7). Accumulators alternate for ILP.
// ---------------------------------------------------------------------------
template<int NC>
__global__ void __launch_bounds__(256) attn_mma_kernel(
    const float* __restrict__ e1pg, const float* __restrict__ e1mg,
    const float* __restrict__ e2pg, const float* __restrict__ e2mg,
    const __half* __restrict__ VtH, const __half* __restrict__ VtL,
    const uint32_t* __restrict__ abits, float* __restrict__ out,
    int outStride, int hshift)
{
    __shared__ __align__(128) char VsH[NC * 128];   // [d][64 j] f16, SW128
    __shared__ __align__(128) char VsL[NC * 128];
    __shared__ float e2ps[64], e2ms[64];
    __shared__ uint32_t aws[128][2];

    const int tid = threadIdx.x;
    const int lane = tid & 31, wid = tid >> 5;
    const int g = blockIdx.y;
    const int b = g >> hshift;
    const int h = g & ((1 << hshift) - 1);
    const int i0 = blockIdx.x * 128;

    const int r0 = wid * 16 + (lane >> 2);   // tile row (0..127)
    const int r1 = r0 + 8;
    const int cq = (lane & 3) * 2;           // fragment col base

    const float E1p0 = e1pg[(size_t)g * PN + i0 + r0];
    const float E1m0 = e1mg[(size_t)g * PN + i0 + r0];
    const float E1p1 = e1pg[(size_t)g * PN + i0 + r1];
    const float E1m1 = e1mg[(size_t)g * PN + i0 + r1];

    const float* e2pp = e2pg + (size_t)g * PN;
    const float* e2mp = e2mg + (size_t)g * PN;
    const __half* vh = VtH + (size_t)g * NC * PN;
    const __half* vl = VtL + (size_t)g * NC * PN;
    const uint32_t* abase = abits + ((size_t)b * PN + i0) * (PN / 32);

    const uint32_t sVH = smem_u32(VsH), sVL = smem_u32(VsL);
    const int vrow_l = ((lane >> 4) << 3) + (lane & 7);
    const int vcol_l = ((lane >> 3) & 1) << 3;

    float acc[NC / 8][4];
#pragma unroll
    for (int nt = 0; nt < NC / 8; nt++)
#pragma unroll
        for (int u = 0; u < 4; u++) acc[nt][u] = 0.f;
    float rs0 = 0.f, rs1 = 0.f;

    for (int c = 0; c < 32; c++) {
        const int j0 = c * 64;
        __syncthreads();                      // previous chunk's reads done
        if (tid < 64) {
            e2ps[tid] = e2pp[j0 + tid];
            e2ms[tid] = e2mp[j0 + tid];
        }
        aws[tid >> 1][tid & 1] =
            abase[(size_t)(tid >> 1) * (PN / 32) + (j0 >> 5) + (tid & 1)];
#pragma unroll
        for (int t = tid; t < NC * 8; t += 256) {
            int d = t >> 3, q = t & 7;
            uint32_t off = d * 128 + q * 16;
            uint32_t sw = off ^ ((off >> 3) & 0x70);
            *(uint4*)(VsH + sw) = *(const uint4*)(vh + (size_t)d * PN + j0 + q * 8);
            *(uint4*)(VsL + sw) = *(const uint4*)(vl + (size_t)d * PN + j0 + q * 8);
        }
        __syncthreads();                      // stages visible

        const uint32_t aw00 = aws[r0][0], aw01 = aws[r0][1];
        const uint32_t aw10 = aws[r1][0], aw11 = aws[r1][1];

#pragma unroll
        for (int ks = 0; ks < 4; ks++) {
            const int cA = ks * 16 + cq;
            const float2 P2a = *(const float2*)&e2ps[cA];
            const float2 M2a = *(const float2*)&e2ms[cA];
            const float2 P2b = *(const float2*)&e2ps[cA + 8];
            const float2 M2b = *(const float2*)&e2ms[cA + 8];
            const uint32_t w0 = (ks < 2) ? aw00 : aw01;
            const uint32_t w1 = (ks < 2) ? aw10 : aw11;
            const int bb = (ks & 1) * 16 + cq;

            float p00 = pel(E1p0, E1m0, P2a.x, M2a.x, w0, bb);
            float p01 = pel(E1p0, E1m0, P2a.y, M2a.y, w0, bb + 1);
            float p02 = pel(E1p0, E1m0, P2b.x, M2b.x, w0, bb + 8);
            float p03 = pel(E1p0, E1m0, P2b.y, M2b.y, w0, bb + 9);
            float p10 = pel(E1p1, E1m1, P2a.x, M2a.x, w1, bb);
            float p11 = pel(E1p1, E1m1, P2a.y, M2a.y, w1, bb + 1);
            float p12 = pel(E1p1, E1m1, P2b.x, M2b.x, w1, bb + 8);
            float p13 = pel(E1p1, E1m1, P2b.y, M2b.y, w1, bb + 9);
            rs0 += (p00 + p01) + (p02 + p03);
            rs1 += (p10 + p11) + (p12 + p13);

            uint32_t a[4];
            a[0] = pack2h(p00, p01);
            a[1] = pack2h(p10, p11);
            a[2] = pack2h(p02, p03);
            a[3] = pack2h(p12, p13);

#pragma unroll
            for (int np = 0; np < NC / 16; np++) {
                int vrow = np * 16 + vrow_l;
                int vcol = ks * 16 + vcol_l;
                uint32_t off = vrow * 128 + vcol * 2;
                off ^= (off >> 3) & 0x70;
                uint32_t bH[4], bL[4];
                ldsm_x4(bH, sVH + off);
                ldsm_x4(bL, sVL + off);
                mma_f16(acc[2 * np],     a, bH);
                mma_f16(acc[2 * np + 1], a, bH + 2);
                mma_f16(acc[2 * np],     a, bL);
                mma_f16(acc[2 * np + 1], a, bL + 2);
            }
        }
    }

    rs0 += __shfl_xor_sync(0xffffffffu, rs0, 1);
    rs0 += __shfl_xor_sync(0xffffffffu, rs0, 2);
    rs1 += __shfl_xor_sync(0xffffffffu, rs1, 1);
    rs1 += __shfl_xor_sync(0xffffffffu, rs1, 2);
    float inv0 = rs0 > 0.f ? 1.f / rs0 : 0.f;
    float inv1 = rs1 > 0.f ? 1.f / rs1 : 0.f;

    float* o0 = out + ((size_t)b * PN + i0 + r0) * outStride + h * NC;
    float* o1 = out + ((size_t)b * PN + i0 + r1) * outStride + h * NC;
#pragma unroll
    for (int nt = 0; nt < NC / 8; nt++) {
        int col = nt * 8 + cq;
        float2 v0 = make_float2(acc[nt][0] * inv0, acc[nt][1] * inv0);
        float2 v1 = make_float2(acc[nt][2] * inv1, acc[nt][3] * inv1);
        v0.x = v0.x > 0.f ? v0.x : expm1f(v0.x);
        v0.y = v0.y > 0.f ? v0.y : expm1f(v0.y);
        v1.x = v1.x > 0.f ? v1.x : expm1f(v1.x);
        v1.y = v1.y > 0.f ? v1.y : expm1f(v1.y);
        *(float2*)(o0 + col) = v0;
        *(float2*)(o1 + col) = v1;
    }
}

// ---------------------------------------------------------------------------
// Kernel 6: Wh2 = h1 @ Wo + factored exps of g1/g2 (expfac fused in epilogue)
// ---------------------------------------------------------------------------
__global__ void gemm2_kernel(const float* __restrict__ h1,
                             const float* __restrict__ Wo,
                             const float* __restrict__ ao1,
                             const float* __restrict__ ao2,
                             float* __restrict__ Wh2,
                             float* __restrict__ e1p, float* __restrict__ e1m,
                             float* __restrict__ e2p, float* __restrict__ e2m)
{
    __shared__ float Wos[PF * PC];
    for (int e = threadIdx.x; e < PF * PC; e += blockDim.x) Wos[e] = Wo[e];
    __syncthreads();

    int wrp = blockIdx.x * (blockDim.x >> 5) + (threadIdx.x >> 5);
    int lane = threadIdx.x & 31;
    int row0 = wrp * 4;
    if (row0 >= PB * PN) return;
    const float* p0 = h1 + (size_t)row0 * PF;

    float a0 = 0.f, a1v = 0.f, a2v = 0.f, a3v = 0.f;
#pragma unroll 4
    for (int k = 0; k < PF; k += 4) {
        float w0 = Wos[(k + 0) * PC + lane];
        float w1 = Wos[(k + 1) * PC + lane];
        float w2 = Wos[(k + 2) * PC + lane];
        float w3 = Wos[(k + 3) * PC + lane];
        float4 x0 = *(const float4*)(p0 + k);
        float4 x1 = *(const float4*)(p0 + PF + k);
        float4 x2 = *(const float4*)(p0 + 2 * PF + k);
        float4 x3 = *(const float4*)(p0 + 3 * PF + k);
        a0  += x0.x * w0 + x0.y * w1 + x0.z * w2 + x0.w * w3;
        a1v += x1.x * w0 + x1.y * w1 + x1.z * w2 + x1.w * w3;
        a2v += x2.x * w0 + x2.y * w1 + x2.z * w2 + x2.w * w3;
        a3v += x3.x * w0 + x3.y * w1 + x3.z * w2 + x3.w * w3;
    }
    Wh2[(size_t)(row0 + 0) * PC + lane] = a0;
    Wh2[(size_t)(row0 + 1) * PC + lane] = a1v;
    Wh2[(size_t)(row0 + 2) * PC + lane] = a2v;
    Wh2[(size_t)(row0 + 3) * PC + lane] = a3v;

    float o1 = ao1[lane], o2 = ao2[lane];
    float s0 = a0 * o1, d0 = a0 * o2;
    float s1 = a1v * o1, d1 = a1v * o2;
    float s2 = a2v * o1, d2 = a2v * o2;
    float s3 = a3v * o1, d3 = a3v * o2;
#pragma unroll
    for (int o = 16; o; o >>= 1) {
        s0 += __shfl_xor_sync(0xffffffffu, s0, o);
        d0 += __shfl_xor_sync(0xffffffffu, d0, o);
        s1 += __shfl_xor_sync(0xffffffffu, s1, o);
        d1 += __shfl_xor_sync(0xffffffffu, d1, o);
        s2 += __shfl_xor_sync(0xffffffffu, s2, o);
        d2 += __shfl_xor_sync(0xffffffffu, d2, o);
        s3 += __shfl_xor_sync(0xffffffffu, s3, o);
        d3 += __shfl_xor_sync(0xffffffffu, d3, o);
    }
    if (lane < 4) {
        float s = (lane == 0) ? s0 : (lane == 1) ? s1 : (lane == 2) ? s2 : s3;
        float d = (lane == 0) ? d0 : (lane == 1) ? d1 : (lane == 2) ? d2 : d3;
        int r = row0 + lane;
        e1p[r] = __expf(s); e1m[r] = __expf(0.2f * s);
        e2p[r] = __expf(d); e2m[r] = __expf(0.2f * d);
    }
}

// ---------------------------------------------------------------------------
// Kernel 7: gather + Linear(32,32) + PReLU + Linear(32,2)
// ---------------------------------------------------------------------------
__global__ void cls_kernel(const float* __restrict__ h2,
                           const int*   __restrict__ idcs,
                           const float* __restrict__ W1,
                           const float* __restrict__ b1,
                           const float* __restrict__ pw,
                           const float* __restrict__ W2,
                           const float* __restrict__ b2,
                           float* __restrict__ out)
{
    int wrp = blockIdx.x * (blockDim.x >> 5) + (threadIdx.x >> 5);
    int lane = threadIdx.x & 31;
    if (wrp >= PB * PK1) return;
    int b = wrp >> 8;
    int idx = idcs[wrp];
    const float* ef = h2 + ((size_t)b * PN + idx) * PC;

    float y = b1[lane];
#pragma unroll
    for (int d = 0; d < PC; d++) y += ef[d] * W1[d * PC + lane];
    y = y > 0.f ? y : pw[lane] * y;

    float o0 = y * W2[lane * 2 + 0];
    float o1 = y * W2[lane * 2 + 1];
#pragma unroll
    for (int o = 16; o; o >>= 1) {
        o0 += __shfl_xor_sync(0xffffffffu, o0, o);
        o1 += __shfl_xor_sync(0xffffffffu, o1, o);
    }
    if (lane == 0) {
        out[wrp * 2 + 0] = o0 + b2[0];
        out[wrp * 2 + 1] = o1 + b2[1];
    }
}

// ---------------------------------------------------------------------------
extern "C" void kernel_launch(void* const* d_in, const int* in_sizes, int n_in,
                              void* d_out, int out_size)
{
    const float* x    = (const float*)d_in[0];
    const int*   adj  = (const int*)  d_in[1];
    const int*   idcs = (const int*)  d_in[2];
    const float* W    = (const float*)d_in[3];
    const float* a1   = (const float*)d_in[4];
    const float* a2   = (const float*)d_in[5];
    const float* Wo   = (const float*)d_in[6];
    const float* ao1  = (const float*)d_in[7];
    const float* ao2  = (const float*)d_in[8];
    const float* W1   = (const float*)d_in[9];
    const float* b1   = (const float*)d_in[10];
    const float* pw   = (const float*)d_in[11];
    const float* W2   = (const float*)d_in[12];
    const float* b2   = (const float*)d_in[13];
    float* out = (float*)d_out;

    float *p_Wh1, *p_h1, *p_Wh2, *p_h2;
    float *p_e1p, *p_e1m, *p_e2p, *p_e2m;
    uint32_t* p_ab;
    __half *p_vh, *p_vl;
    cudaGetSymbolAddress((void**)&p_Wh1, g_Wh1);
    cudaGetSymbolAddress((void**)&p_h1,  g_h1);
    cudaGetSymbolAddress((void**)&p_Wh2, g_Wh2);
    cudaGetSymbolAddress((void**)&p_h2,  g_h2);
    cudaGetSymbolAddress((void**)&p_ab,  g_abits);
    cudaGetSymbolAddress((void**)&p_vh,  g_VtH);
    cudaGetSymbolAddress((void**)&p_vl,  g_VtL);
    cudaGetSymbolAddress((void**)&p_e1p, g_e1p);
    cudaGetSymbolAddress((void**)&p_e1m, g_e1m);
    cudaGetSymbolAddress((void**)&p_e2p, g_e2p);
    cudaGetSymbolAddress((void**)&p_e2m, g_e2m);

    gemm1_kernel<<<dim3(PN / 64, PB * PH), 256>>>(x, W, p_Wh1);
    f12_kernel<<<(PB * PH * PN) / 8, 256>>>(p_Wh1, a1, a2,
                                            p_e1p, p_e1m, p_e2p, p_e2m);
    adjbits_kernel<<<(PB * PN * PN) / 256, 256>>>(adj, p_ab);
    tsplit_kernel<PD><<<dim3(PN / 128, PB * PH), 256>>>(p_Wh1, p_vh, p_vl);

    attn_mma_kernel<PD><<<dim3(PN / 128, PB * PH), 256>>>(
        p_e1p, p_e1m, p_e2p, p_e2m, p_vh, p_vl, p_ab, p_h1, PH * PD, 2);

    gemm2_kernel<<<(PB * PN / 4) / 8, 256>>>(p_h1, Wo, ao1, ao2, p_Wh2,
                                             p_e1p, p_e1m, p_e2p, p_e2m);
    tsplit_kernel<PC><<<dim3(PN / 128, PB), 256>>>(p_Wh2, p_vh, p_vl);

    attn_mma_kernel<PC><<<dim3(PN / 128, PB), 256>>>(
        p_e1p, p_e1m, p_e2p, p_e2m, p_vh, p_vl, p_ab, p_h2, PC, 0);

    cls_kernel<<<(PB * PK1) / 8, 256>>>(p_h2, idcs, W1, b1, pw, W2, b2, out);
}

// round 11
// speedup vs baseline: 3.5180x; 1.3046x over previous
#include <cuda_runtime.h>
#include <cuda_fp16.h>
#include <math.h>
#include <stdint.h>

// Problem constants
#define PB 4
#define PN 2048
#define PF 256
#define PD 64      // NHID
#define PH 4       // NHEADS
#define PC 32      // NCLASS
#define PK1 256

// ---------------- scratch (device globals, no allocation) ----------------
__device__ float g_h1[PB * PN * PH * PD];          // layer-1 concat output (fp32)
__device__ float g_h2[PB * PN * PC];
__device__ uint32_t g_abits[PB * PN * (PN / 32)];  // adjacency bitmask
__device__ __half g_VtH[PB * PH * PD * PN];        // [g][d][n] fp16 (reused by layer 2)
__device__ __half g_e1p[PB * PH * PN];             // factored exps, fp16
__device__ __half g_e1m[PB * PH * PN];
__device__ __half g_e2p[PB * PH * PN];
__device__ __half g_e2m[PB * PH * PN];

// =========================== helpers ===================================
__device__ __forceinline__ uint32_t smem_u32(const void* p) {
    uint32_t a;
    asm("{ .reg .u64 t; cvta.to.shared.u64 t, %1; cvt.u32.u64 %0, t; }"
        : "=r"(a) : "l"(p));
    return a;
}
// pack2h(lo, hi): f16x2 with lo in bits[0:16)
__device__ __forceinline__ uint32_t pack2h(float lo, float hi) {
    uint32_t r;
    asm("cvt.rn.f16x2.f32 %0, %1, %2;" : "=r"(r) : "f"(hi), "f"(lo));
    return r;
}
__device__ __forceinline__ void mma_f16(float* d, const uint32_t* a, const uint32_t* b) {
    asm volatile(
        "mma.sync.aligned.m16n8k16.row.col.f32.f16.f16.f32 "
        "{%0,%1,%2,%3}, {%4,%5,%6,%7}, {%8,%9}, {%0,%1,%2,%3};"
        : "+f"(d[0]), "+f"(d[1]), "+f"(d[2]), "+f"(d[3])
        : "r"(a[0]), "r"(a[1]), "r"(a[2]), "r"(a[3]), "r"(b[0]), "r"(b[1]));
}
__device__ __forceinline__ void ldsm_x4(uint32_t* r, uint32_t addr) {
    asm volatile("ldmatrix.sync.aligned.m8n8.x4.shared.b16 {%0,%1,%2,%3}, [%4];"
                 : "=r"(r[0]), "=r"(r[1]), "=r"(r[2]), "=r"(r[3]) : "r"(addr));
}
// 2-bit -> per-half mask32: bit0 -> 0x0000FFFF, bit1 -> 0xFFFF0000
// NOTE: isolate the two bits FIRST (R9 bug: bit bb+16 leaked into high half).
__device__ __forceinline__ uint32_t mask2(uint32_t w, int bb) {
    uint32_t y = (w >> bb) & 3u;
    return ((y | (y << 15)) & 0x00010001u) * 0xFFFFu;
}
// p = max(e1p*e2p, e1m*e2m) packed fp16x2 (== exp(leakyrelu(f1+f2)))
__device__ __forceinline__ uint32_t pmax2(__half2 e1p, __half2 e1m,
                                          uint32_t e2p, uint32_t e2m) {
    __half2 a = __hmul2(e1p, *(__half2*)&e2p);
    __half2 b = __hmul2(e1m, *(__half2*)&e2m);
    __half2 m = __hmax2(a, b);
    return *(uint32_t*)&m;
}

// ---------------------------------------------------------------------------
// Kernel 1: Wh1 = x @ W[h] with FUSED epilogue:
//   - f1/f2 row dots + factored exps (fp16) -> e1p/e1m/e2p/e2m
//   - transpose + fp16 convert -> VtH[g][d][n]
// No fp32 Wh1 global at all.
// ---------------------------------------------------------------------------
__global__ void gemm1_kernel(const float* __restrict__ x,
                             const float* __restrict__ W,
                             const float* __restrict__ a1,
                             const float* __restrict__ a2,
                             __half* __restrict__ VtH,
                             __half* __restrict__ e1p, __half* __restrict__ e1m,
                             __half* __restrict__ e2p, __half* __restrict__ e2m)
{
    __shared__ __align__(16) float As[32][68];  // 8704 B (reused by epilogue)
    __shared__ __align__(16) float Bs[32][64];  // 8192 B

    const int it = blockIdx.x;
    const int bh = blockIdx.y;
    const int b  = bh >> 2;
    const int h  = bh & 3;
    const int i0 = it * 64;
    const int tid = threadIdx.x;
    const int tx = tid & 15, ty = tid >> 4;

    const float* A  = x + ((size_t)b * PN + i0) * PF;
    const float* Bw = W + (size_t)h * PF * PD;

    float acc[4][4];
#pragma unroll
    for (int u = 0; u < 4; u++)
#pragma unroll
        for (int v = 0; v < 4; v++) acc[u][v] = 0.f;

    for (int k0 = 0; k0 < PF; k0 += 32) {
        __syncthreads();
#pragma unroll
        for (int r = 0; r < 8; r++) {
            int e = tid + 256 * r;
            int row = e >> 5, col = e & 31;
            As[col][row] = A[(size_t)row * PF + k0 + col];
        }
#pragma unroll
        for (int r = 0; r < 8; r++) {
            int e = tid + 256 * r;
            int k = e >> 6, d = e & 63;
            Bs[k][d] = Bw[(size_t)(k0 + k) * PD + d];
        }
        __syncthreads();
#pragma unroll
        for (int k = 0; k < 32; k++) {
            float4 pa = *(const float4*)&As[k][ty * 4];
            float4 pb = *(const float4*)&Bs[k][tx * 4];
            acc[0][0] += pa.x * pb.x; acc[0][1] += pa.x * pb.y;
            acc[0][2] += pa.x * pb.z; acc[0][3] += pa.x * pb.w;
            acc[1][0] += pa.y * pb.x; acc[1][1] += pa.y * pb.y;
            acc[1][2] += pa.y * pb.z; acc[1][3] += pa.y * pb.w;
            acc[2][0] += pa.z * pb.x; acc[2][1] += pa.z * pb.y;
            acc[2][2] += pa.z * pb.z; acc[2][3] += pa.z * pb.w;
            acc[3][0] += pa.w * pb.x; acc[3][1] += pa.w * pb.y;
            acc[3][2] += pa.w * pb.z; acc[3][3] += pa.w * pb.w;
        }
    }

    // ---- epilogue stage 1: f1/f2 partials -> reduce -> exps ----
    const float4 A1 = *(const float4*)&a1[h * PD + tx * 4];
    const float4 A2 = *(const float4*)&a2[h * PD + tx * 4];
    __syncthreads();
    float* S1 = &As[0][0];   // [64][17]
    float* S2 = &Bs[0][0];   // [64][17]
#pragma unroll
    for (int u = 0; u < 4; u++) {
        int row = ty * 4 + u;
        S1[row * 17 + tx] = acc[u][0] * A1.x + acc[u][1] * A1.y
                          + acc[u][2] * A1.z + acc[u][3] * A1.w;
        S2[row * 17 + tx] = acc[u][0] * A2.x + acc[u][1] * A2.y
                          + acc[u][2] * A2.z + acc[u][3] * A2.w;
    }
    __syncthreads();
    if (tid < 64) {
        float f1 = 0.f, f2 = 0.f;
#pragma unroll
        for (int t = 0; t < 16; t++) { f1 += S1[tid * 17 + t]; f2 += S2[tid * 17 + t]; }
        size_t o = (size_t)bh * PN + i0 + tid;
        e1p[o] = __float2half(__expf(f1));
        e1m[o] = __float2half(__expf(0.2f * f1));
        e2p[o] = __float2half(__expf(f2));
        e2m[o] = __float2half(__expf(0.2f * f2));
    }
    __syncthreads();

    // ---- epilogue stage 2: transpose + fp16 -> VtH[bh][d][n] ----
    __half* T = (__half*)&As[0][0];   // [64][68] halves = 8704 B
#pragma unroll
    for (int v = 0; v < 4; v++) {
        uint2 tv;
        tv.x = pack2h(acc[0][v], acc[1][v]);
        tv.y = pack2h(acc[2][v], acc[3][v]);
        *(uint2*)&T[(tx * 4 + v) * 68 + ty * 4] = tv;
    }
    __syncthreads();
#pragma unroll
    for (int r = 0; r < 4; r++) {
        int e = tid + 256 * r;     // 1024 uint2 total: 64 d x 16
        int d = e >> 4, q = e & 15;
        *(uint2*)(VtH + ((size_t)bh * PD + d) * PN + i0 + q * 4) =
            *(const uint2*)&T[d * 68 + q * 4];
    }
}

// ---------------------------------------------------------------------------
// Kernel 2: pack adj>0 into bitmask
// ---------------------------------------------------------------------------
__global__ void adjbits_kernel(const int* __restrict__ adj,
                               uint32_t* __restrict__ bits)
{
    size_t t = (size_t)blockIdx.x * 256 + threadIdx.x;
    int a = adj[t];
    unsigned m = __ballot_sync(0xffffffffu, a > 0);
    if ((threadIdx.x & 31) == 0) bits[t >> 5] = m;
}

// ---------------------------------------------------------------------------
// Kernel 3: warp-MMA attention (single fp16 V, max-trick fp16 P build,
//   rowsum via ones-column mma, register prefetch of next chunk).
//   Block = 256 thr = 8 warps x 16 rows = 128 rows; 32 j-chunks of 64.
// ---------------------------------------------------------------------------
template<int NC>
__global__ void __launch_bounds__(256) attn_mma_kernel(
    const __half* __restrict__ e1pg, const __half* __restrict__ e1mg,
    const __half* __restrict__ e2pg, const __half* __restrict__ e2mg,
    const __half* __restrict__ Vt, const uint32_t* __restrict__ abits,
    float* __restrict__ out, int outStride, int hshift)
{
    __shared__ __align__(128) char Vs[NC * 128];   // [d][64 j] f16, SW128
    __shared__ uint2 es[32];                       // {e2p pair, e2m pair} per j-pair
    __shared__ uint32_t aws[128][2];

    const int tid = threadIdx.x;
    const int lane = tid & 31, wid = tid >> 5;
    const int g = blockIdx.y;
    const int b = g >> hshift;
    const int h = g & ((1 << hshift) - 1);
    const int i0 = blockIdx.x * 128;

    const int r0 = wid * 16 + (lane >> 2);   // tile row (0..127)
    const int r1 = r0 + 8;
    const int cq = (lane & 3) * 2;

    const __half2 E1p0 = __half2half2(e1pg[(size_t)g * PN + i0 + r0]);
    const __half2 E1m0 = __half2half2(e1mg[(size_t)g * PN + i0 + r0]);
    const __half2 E1p1 = __half2half2(e1pg[(size_t)g * PN + i0 + r1]);
    const __half2 E1m1 = __half2half2(e1mg[(size_t)g * PN + i0 + r1]);

    const uint32_t* pp = (const uint32_t*)(e2pg + (size_t)g * PN);
    const uint32_t* mm = (const uint32_t*)(e2mg + (size_t)g * PN);
    const __half* vbase = Vt + (size_t)g * NC * PN;
    const uint32_t* abase = abits + ((size_t)b * PN + i0) * (PN / 32);

    const uint32_t sVs = smem_u32(Vs);
    const int vrow_l = ((lane >> 4) << 3) + (lane & 7);
    const int vcol_l = ((lane >> 3) & 1) << 3;
    const uint32_t ONES2[2] = {0x3C003C00u, 0x3C003C00u};

    constexpr int VR = NC / 32;    // uint4 prefetch regs per thread
    uint4 vr[VR];
    uint2 er;
    uint32_t ar;

    // prefetch chunk 0
    {
        const int j0 = 0;
#pragma unroll
        for (int r = 0; r < VR; r++) {
            int e = tid + 256 * r;
            int d = e >> 3, q = e & 7;
            vr[r] = *(const uint4*)(vbase + (size_t)d * PN + j0 + q * 8);
        }
        int l5 = tid & 31;
        er.x = pp[j0 / 2 + l5];
        er.y = mm[j0 / 2 + l5];
        ar = abase[(size_t)(tid >> 1) * (PN / 32) + (j0 >> 5) + (tid & 1)];
    }

    float acc[NC / 8][4];
#pragma unroll
    for (int nt = 0; nt < NC / 8; nt++)
#pragma unroll
        for (int u = 0; u < 4; u++) acc[nt][u] = 0.f;
    float accS[4] = {0.f, 0.f, 0.f, 0.f};

    for (int c = 0; c < 32; c++) {
        __syncthreads();                       // previous chunk's readers done
        // stage prefetched data
#pragma unroll
        for (int r = 0; r < VR; r++) {
            int e = tid + 256 * r;
            int d = e >> 3, q = e & 7;
            uint32_t off = d * 128 + q * 16;
            uint32_t sw = off ^ ((off >> 3) & 0x70);
            *(uint4*)(Vs + sw) = vr[r];
        }
        if (tid < 32) es[tid] = er;
        aws[tid >> 1][tid & 1] = ar;
        __syncthreads();                       // stage visible

        // prefetch next chunk (hidden behind compute)
        if (c + 1 < 32) {
            const int j0n = (c + 1) * 64;
#pragma unroll
            for (int r = 0; r < VR; r++) {
                int e = tid + 256 * r;
                int d = e >> 3, q = e & 7;
                vr[r] = *(const uint4*)(vbase + (size_t)d * PN + j0n + q * 8);
            }
            int l5 = tid & 31;
            er.x = pp[j0n / 2 + l5];
            er.y = mm[j0n / 2 + l5];
            ar = abase[(size_t)(tid >> 1) * (PN / 32) + (j0n >> 5) + (tid & 1)];
        }

        const uint32_t aw00 = aws[r0][0], aw01 = aws[r0][1];
        const uint32_t aw10 = aws[r1][0], aw11 = aws[r1][1];

#pragma unroll
        for (int ks = 0; ks < 4; ks++) {
            const uint2 ea = es[ks * 8 + (lane & 3)];
            const uint2 eb = es[ks * 8 + (lane & 3) + 4];
            const uint32_t w0 = (ks < 2) ? aw00 : aw01;
            const uint32_t w1 = (ks < 2) ? aw10 : aw11;
            const int bb = (ks & 1) * 16 + cq;

            uint32_t a[4];
            a[0] = pmax2(E1p0, E1m0, ea.x, ea.y) & mask2(w0, bb);      // r0, j cq..cq+1
            a[1] = pmax2(E1p1, E1m1, ea.x, ea.y) & mask2(w1, bb);      // r1
            a[2] = pmax2(E1p0, E1m0, eb.x, eb.y) & mask2(w0, bb + 8);  // r0, +8
            a[3] = pmax2(E1p1, E1m1, eb.x, eb.y) & mask2(w1, bb + 8);  // r1, +8

            mma_f16(accS, a, ONES2);           // row sums (exact fp32 accum)

#pragma unroll
            for (int np = 0; np < NC / 16; np++) {
                int vrow = np * 16 + vrow_l;
                int vcol = ks * 16 + vcol_l;
                uint32_t off = vrow * 128 + vcol * 2;
                off ^= (off >> 3) & 0x70;
                uint32_t bH[4];
                ldsm_x4(bH, sVs + off);
                mma_f16(acc[2 * np],     a, bH);
                mma_f16(acc[2 * np + 1], a, bH + 2);
            }
        }
    }

    // accS columns all equal the row sum; no cross-lane reduction needed
    float inv0 = accS[0] > 0.f ? 1.f / accS[0] : 0.f;
    float inv1 = accS[2] > 0.f ? 1.f / accS[2] : 0.f;

    float* o0 = out + ((size_t)b * PN + i0 + r0) * outStride + h * NC;
    float* o1 = out + ((size_t)b * PN + i0 + r1) * outStride + h * NC;
#pragma unroll
    for (int nt = 0; nt < NC / 8; nt++) {
        int col = nt * 8 + cq;
        float2 v0 = make_float2(acc[nt][0] * inv0, acc[nt][1] * inv0);
        float2 v1 = make_float2(acc[nt][2] * inv1, acc[nt][3] * inv1);
        v0.x = v0.x > 0.f ? v0.x : expm1f(v0.x);
        v0.y = v0.y > 0.f ? v0.y : expm1f(v0.y);
        v1.x = v1.x > 0.f ? v1.x : expm1f(v1.x);
        v1.y = v1.y > 0.f ? v1.y : expm1f(v1.y);
        *(float2*)(o0 + col) = v0;
        *(float2*)(o1 + col) = v1;
    }
}

// ---------------------------------------------------------------------------
// Kernel 4: Wh2 = h1 @ Wo, fused: transposed fp16 V write + factored exps.
// Warp per 4 rows.
// ---------------------------------------------------------------------------
__global__ void gemm2_kernel(const float* __restrict__ h1,
                             const float* __restrict__ Wo,
                             const float* __restrict__ ao1,
                             const float* __restrict__ ao2,
                             __half* __restrict__ Vt2,
                             __half* __restrict__ e1p, __half* __restrict__ e1m,
                             __half* __restrict__ e2p, __half* __restrict__ e2m)
{
    __shared__ float Wos[PF * PC];
    for (int e = threadIdx.x; e < PF * PC; e += blockDim.x) Wos[e] = Wo[e];
    __syncthreads();

    int wrp = blockIdx.x * (blockDim.x >> 5) + (threadIdx.x >> 5);
    int lane = threadIdx.x & 31;
    int row0 = wrp * 4;
    if (row0 >= PB * PN) return;
    const float* p0 = h1 + (size_t)row0 * PF;

    float a0 = 0.f, a1v = 0.f, a2v = 0.f, a3v = 0.f;
#pragma unroll 4
    for (int k = 0; k < PF; k += 4) {
        float w0 = Wos[(k + 0) * PC + lane];
        float w1 = Wos[(k + 1) * PC + lane];
        float w2 = Wos[(k + 2) * PC + lane];
        float w3 = Wos[(k + 3) * PC + lane];
        float4 x0 = *(const float4*)(p0 + k);
        float4 x1 = *(const float4*)(p0 + PF + k);
        float4 x2 = *(const float4*)(p0 + 2 * PF + k);
        float4 x3 = *(const float4*)(p0 + 3 * PF + k);
        a0  += x0.x * w0 + x0.y * w1 + x0.z * w2 + x0.w * w3;
        a1v += x1.x * w0 + x1.y * w1 + x1.z * w2 + x1.w * w3;
        a2v += x2.x * w0 + x2.y * w1 + x2.z * w2 + x2.w * w3;
        a3v += x3.x * w0 + x3.y * w1 + x3.z * w2 + x3.w * w3;
    }
    // transposed fp16 V write: Vt2[b][c=lane][n]
    {
        int bb = row0 >> 11;           // row0 / PN
        int n  = row0 & (PN - 1);
        uint2 tv;
        tv.x = pack2h(a0, a1v);
        tv.y = pack2h(a2v, a3v);
        *(uint2*)(Vt2 + ((size_t)bb * PC + lane) * PN + n) = tv;
    }

    float o1 = ao1[lane], o2 = ao2[lane];
    float s0 = a0 * o1, d0 = a0 * o2;
    float s1 = a1v * o1, d1 = a1v * o2;
    float s2 = a2v * o1, d2 = a2v * o2;
    float s3 = a3v * o1, d3 = a3v * o2;
#pragma unroll
    for (int o = 16; o; o >>= 1) {
        s0 += __shfl_xor_sync(0xffffffffu, s0, o);
        d0 += __shfl_xor_sync(0xffffffffu, d0, o);
        s1 += __shfl_xor_sync(0xffffffffu, s1, o);
        d1 += __shfl_xor_sync(0xffffffffu, d1, o);
        s2 += __shfl_xor_sync(0xffffffffu, s2, o);
        d2 += __shfl_xor_sync(0xffffffffu, d2, o);
        s3 += __shfl_xor_sync(0xffffffffu, s3, o);
        d3 += __shfl_xor_sync(0xffffffffu, d3, o);
    }
    if (lane < 4) {
        float s = (lane == 0) ? s0 : (lane == 1) ? s1 : (lane == 2) ? s2 : s3;
        float d = (lane == 0) ? d0 : (lane == 1) ? d1 : (lane == 2) ? d2 : d3;
        int r = row0 + lane;
        e1p[r] = __float2half(__expf(s));
        e1m[r] = __float2half(__expf(0.2f * s));
        e2p[r] = __float2half(__expf(d));
        e2m[r] = __float2half(__expf(0.2f * d));
    }
}

// ---------------------------------------------------------------------------
// Kernel 5: gather + Linear(32,32) + PReLU + Linear(32,2)
// ---------------------------------------------------------------------------
__global__ void cls_kernel(const float* __restrict__ h2,
                           const int*   __restrict__ idcs,
                           const float* __restrict__ W1,
                           const float* __restrict__ b1,
                           const float* __restrict__ pw,
                           const float* __restrict__ W2,
                           const float* __restrict__ b2,
                           float* __restrict__ out)
{
    int wrp = blockIdx.x * (blockDim.x >> 5) + (threadIdx.x >> 5);
    int lane = threadIdx.x & 31;
    if (wrp >= PB * PK1) return;
    int b = wrp >> 8;
    int idx = idcs[wrp];
    const float* ef = h2 + ((size_t)b * PN + idx) * PC;

    float y = b1[lane];
#pragma unroll
    for (int d = 0; d < PC; d++) y += ef[d] * W1[d * PC + lane];
    y = y > 0.f ? y : pw[lane] * y;

    float o0 = y * W2[lane * 2 + 0];
    float o1 = y * W2[lane * 2 + 1];
#pragma unroll
    for (int o = 16; o; o >>= 1) {
        o0 += __shfl_xor_sync(0xffffffffu, o0, o);
        o1 += __shfl_xor_sync(0xffffffffu, o1, o);
    }
    if (lane == 0) {
        out[wrp * 2 + 0] = o0 + b2[0];
        out[wrp * 2 + 1] = o1 + b2[1];
    }
}

// ---------------------------------------------------------------------------
extern "C" void kernel_launch(void* const* d_in, const int* in_sizes, int n_in,
                              void* d_out, int out_size)
{
    const float* x    = (const float*)d_in[0];
    const int*   adj  = (const int*)  d_in[1];
    const int*   idcs = (const int*)  d_in[2];
    const float* W    = (const float*)d_in[3];
    const float* a1   = (const float*)d_in[4];
    const float* a2   = (const float*)d_in[5];
    const float* Wo   = (const float*)d_in[6];
    const float* ao1  = (const float*)d_in[7];
    const float* ao2  = (const float*)d_in[8];
    const float* W1   = (const float*)d_in[9];
    const float* b1   = (const float*)d_in[10];
    const float* pw   = (const float*)d_in[11];
    const float* W2   = (const float*)d_in[12];
    const float* b2   = (const float*)d_in[13];
    float* out = (float*)d_out;

    float *p_h1, *p_h2;
    __half *p_vh, *p_e1p, *p_e1m, *p_e2p, *p_e2m;
    uint32_t* p_ab;
    cudaGetSymbolAddress((void**)&p_h1,  g_h1);
    cudaGetSymbolAddress((void**)&p_h2,  g_h2);
    cudaGetSymbolAddress((void**)&p_ab,  g_abits);
    cudaGetSymbolAddress((void**)&p_vh,  g_VtH);
    cudaGetSymbolAddress((void**)&p_e1p, g_e1p);
    cudaGetSymbolAddress((void**)&p_e1m, g_e1m);
    cudaGetSymbolAddress((void**)&p_e2p, g_e2p);
    cudaGetSymbolAddress((void**)&p_e2m, g_e2m);

    gemm1_kernel<<<dim3(PN / 64, PB * PH), 256>>>(x, W, a1, a2, p_vh,
                                                  p_e1p, p_e1m, p_e2p, p_e2m);
    adjbits_kernel<<<(PB * PN * PN) / 256, 256>>>(adj, p_ab);

    attn_mma_kernel<PD><<<dim3(PN / 128, PB * PH), 256>>>(
        p_e1p, p_e1m, p_e2p, p_e2m, p_vh, p_ab, p_h1, PH * PD, 2);

    gemm2_kernel<<<(PB * PN / 4) / 8, 256>>>(p_h1, Wo, ao1, ao2, p_vh,
                                             p_e1p, p_e1m, p_e2p, p_e2m);

    attn_mma_kernel<PC><<<dim3(PN / 128, PB), 256>>>(
        p_e1p, p_e1m, p_e2p, p_e2m, p_vh, p_ab, p_h2, PC, 0);

    cls_kernel<<<(PB * PK1) / 8, 256>>>(p_h2, idcs, W1, b1, pw, W2, b2, out);
}